// round 16
// baseline (speedup 1.0000x reference)
#include <cuda_runtime.h>
#include <cuda_bf16.h>
#include <cuda_fp16.h>
#include <cstdint>

// Problem constants (fixed shapes from setup_inputs)
static constexpr int B_    = 8;
static constexpr int C_    = 256;
static constexpr int N_    = 1024;   // T*H*W
static constexpr int HEADS = 8;
static constexpr int DK    = 1024;   // KC / heads
static constexpr int DV    = 64;     // VC / heads
static constexpr int KC    = 8192;
static constexpr int VC    = 512;
static constexpr int CHUNKSZ = 128;
static constexpr int NCHUNK  = 8;

// Device scratch (no cudaMalloc allowed)
__device__ __half g_A2f[(size_t)B_ * HEADS * C_ * C_];     // A^T fp16 [b,h][c'][c]
__device__ __half g_Pf[(size_t)B_ * HEADS * DK * C_];      // P fp16 [b,h][i][c']
__device__ __half g_Vf[(size_t)B_ * VC * N_];              // V fp16 [b][d][i]
__device__ __half g_Xf[(size_t)B_ * N_ * C_];              // x^T fp16 [b][j][c]
__device__ __half g_x16[(size_t)B_ * C_ * N_];             // x fp16 [b][c][j]
__device__ __half g_o2T[(size_t)B_ * N_ * VC];             // O^T fp16 [b][j][d]
__device__ __half g_WqThi[(size_t)HEADS * C_ * DK];        // Wq^T fp16 [h][c'][m]
__device__ __half g_Wkhi[(size_t)KC * C_];                 // Wk fp16 [dk][c]
__device__ __half g_Wvhi[(size_t)VC * C_];
__device__ __half g_Wvlo[(size_t)VC * C_];
__device__ __half g_Wrhi[(size_t)C_ * VC];
__device__ __half g_Wrlo[(size_t)C_ * VC];

// ---------------------------------------------------------------------------
// Helpers
// ---------------------------------------------------------------------------
__device__ __forceinline__ float fp16hi(float f)
{
    return __half2float(__float2half_rn(f));
}
__device__ __forceinline__ uint32_t packh(float lo_el, float hi_el)
{
    __half2 h = __floats2half2_rn(lo_el, hi_el);
    return *reinterpret_cast<uint32_t*>(&h);
}
__device__ __forceinline__ void mma16816h(float* d, const uint32_t* a, const uint32_t* b)
{
    asm volatile(
        "mma.sync.aligned.m16n8k16.row.col.f32.f16.f16.f32 "
        "{%0,%1,%2,%3}, {%4,%5,%6,%7}, {%8,%9}, {%0,%1,%2,%3};"
        : "+f"(d[0]), "+f"(d[1]), "+f"(d[2]), "+f"(d[3])
        : "r"(a[0]), "r"(a[1]), "r"(a[2]), "r"(a[3]), "r"(b[0]), "r"(b[1]));
}
// fp16-accumulator MMA
__device__ __forceinline__ void mma16816hh(uint32_t* d, const uint32_t* a, const uint32_t* b)
{
    asm volatile(
        "mma.sync.aligned.m16n8k16.row.col.f16.f16.f16.f16 "
        "{%0,%1}, {%2,%3,%4,%5}, {%6,%7}, {%0,%1};"
        : "+r"(d[0]), "+r"(d[1])
        : "r"(a[0]), "r"(a[1]), "r"(a[2]), "r"(a[3]), "r"(b[0]), "r"(b[1]));
}
__device__ __forceinline__ void ldsm4(uint32_t* r, uint32_t a)
{
    asm volatile("ldmatrix.sync.aligned.m8n8.x4.shared.b16 {%0,%1,%2,%3}, [%4];"
                 : "=r"(r[0]), "=r"(r[1]), "=r"(r[2]), "=r"(r[3]) : "r"(a));
}
__device__ __forceinline__ uint32_t movm_t(uint32_t a)
{
    uint32_t d;
    asm("movmatrix.sync.aligned.m8n8.trans.b16 %0, %1;" : "=r"(d) : "r"(a));
    return d;
}
__device__ __forceinline__ void stsm2(uint32_t addr, uint32_t r0, uint32_t r1)
{
    asm volatile("stmatrix.sync.aligned.m8n8.x2.shared.b16 [%0], {%1,%2};"
                 :: "r"(addr), "r"(r0), "r"(r1) : "memory");
}
__device__ __forceinline__ uint32_t smem_u32(const void* p)
{
    uint32_t a;
    asm("{ .reg .u64 t; cvta.to.shared.u64 t, %1; cvt.u32.u64 %0, t; }"
        : "=r"(a) : "l"(p));
    return a;
}
__device__ __forceinline__ void cp16(uint32_t dst, const void* src)
{
    asm volatile("cp.async.cg.shared.global [%0], [%1], 16;"
                 :: "r"(dst), "l"(src));
}
#define CP_COMMIT() asm volatile("cp.async.commit_group;" ::: "memory")
#define CP_WAIT1()  asm volatile("cp.async.wait_group 1;" ::: "memory")
#define CP_WAIT0()  asm volatile("cp.async.wait_group 0;" ::: "memory")

// smem strides (u32 words)
static constexpr int SW64 = 36;  // 32 payload + 4 pad (64 fp16 per row)
static constexpr int SWP  = 68;  // 64 payload + 4 pad
static constexpr int SWV  = 68;

// attn smem layout (u32 word offsets)
static constexpr int BUFW    = 2 * 128 * SW64;            // 9216 per buffer (P+X)
static constexpr int OFF_V   = 2 * BUFW;                  // 18432; 2 V buffers
static constexpr int VBUFW   = 64 * SWV;                  // 4352 per V buffer
static constexpr int OFF_RED = OFF_V + 2 * VBUFW;         // 27136
static constexpr int SMEM_WORDS_ATTN = OFF_RED + 512;     // 27648 words = 110592 B
// Pa tile (128*SWP = 8704 words) aliases buffer0.

// mgemm2: per K=64 stage, tiles of 128 rows x 64 fp16
static constexpr int MG_TILE = 128 * SW64;                // 4608 words per tile

// ---------------------------------------------------------------------------
// Prep: elementwise fp16 conversions
// ---------------------------------------------------------------------------
static constexpr int F4_WK = (KC * C_) / 4;
static constexpr int F4_WV = (VC * C_) / 4;
static constexpr int F4_WR = (C_ * VC) / 4;
static constexpr int F4_X  = (B_ * C_ * N_) / 4;
static constexpr int F4_TOTAL = F4_WK + F4_WV + F4_WR + F4_X;

__global__ __launch_bounds__(256)
void prep_elem_kernel(const float* __restrict__ Wk, const float* __restrict__ Wv,
                      const float* __restrict__ Wr, const float* __restrict__ x)
{
    int i4 = blockIdx.x * 256 + threadIdx.x;
    if (i4 >= F4_TOTAL) return;
    if (i4 < F4_WK) {
        float4 f = reinterpret_cast<const float4*>(Wk)[i4];
        uint32_t* H = reinterpret_cast<uint32_t*>(g_Wkhi);
        H[i4 * 2]     = packh(f.x, f.y);
        H[i4 * 2 + 1] = packh(f.z, f.w);
        return;
    }
    const float* src;
    uint32_t *H, *L;
    int j4;
    if (i4 < F4_WK + F4_WV) {
        j4 = i4 - F4_WK; src = Wv;
        H = reinterpret_cast<uint32_t*>(g_Wvhi);
        L = reinterpret_cast<uint32_t*>(g_Wvlo);
    } else if (i4 < F4_WK + F4_WV + F4_WR) {
        j4 = i4 - F4_WK - F4_WV; src = Wr;
        H = reinterpret_cast<uint32_t*>(g_Wrhi);
        L = reinterpret_cast<uint32_t*>(g_Wrlo);
    } else {
        j4 = i4 - F4_WK - F4_WV - F4_WR;
        float4 f = reinterpret_cast<const float4*>(x)[j4];
        uint32_t* Hx = reinterpret_cast<uint32_t*>(g_x16);
        Hx[j4 * 2]     = packh(f.x, f.y);
        Hx[j4 * 2 + 1] = packh(f.z, f.w);
        return;
    }
    float4 f = reinterpret_cast<const float4*>(src)[j4];
    float h0 = fp16hi(f.x), h1 = fp16hi(f.y), h2 = fp16hi(f.z), h3 = fp16hi(f.w);
    H[j4 * 2]     = packh(h0, h1);
    H[j4 * 2 + 1] = packh(h2, h3);
    L[j4 * 2]     = packh(f.x - h0, f.y - h1);
    L[j4 * 2 + 1] = packh(f.z - h2, f.w - h3);
}

// ---------------------------------------------------------------------------
// Prep: Wq^T fp16
// ---------------------------------------------------------------------------
__global__ __launch_bounds__(256)
void prep_wqt_kernel(const float* __restrict__ Wq)
{
    __shared__ float tile[32][33];
    const int h  = blockIdx.z;
    const int c0 = blockIdx.y * 32;
    const int m0 = blockIdx.x * 32;
    const int txx = threadIdx.x & 31;
    const int tyy = threadIdx.x >> 5;

#pragma unroll
    for (int i = 0; i < 4; ++i) {
        int m = m0 + tyy + i * 8;
        tile[tyy + i * 8][txx] = Wq[(size_t)(h * DK + m) * C_ + c0 + txx];
    }
    __syncthreads();
#pragma unroll
    for (int i = 0; i < 4; ++i) {
        int c = c0 + tyy + i * 8;
        g_WqThi[((size_t)h * C_ + c) * DK + m0 + txx] =
            __float2half_rn(tile[txx][tyy + i * 8]);
    }
}

// ---------------------------------------------------------------------------
// x transpose: x [b][c][j] fp32 -> g_Xf [b][j][c] fp16
// ---------------------------------------------------------------------------
__global__ __launch_bounds__(256)
void xsplit_kernel(const float* __restrict__ x)
{
    __shared__ float tile[32][33];
    const int b  = blockIdx.z;
    const int c0 = blockIdx.y * 32;
    const int j0 = blockIdx.x * 32;
    const int txx = threadIdx.x & 31;
    const int tyy = threadIdx.x >> 5;

#pragma unroll
    for (int i = 0; i < 4; ++i) {
        int c = c0 + tyy + i * 8;
        tile[tyy + i * 8][txx] = x[((size_t)b * C_ + c) * N_ + j0 + txx];
    }
    __syncthreads();
#pragma unroll
    for (int i = 0; i < 4; ++i) {
        int j = j0 + tyy + i * 8;
        g_Xf[((size_t)b * N_ + j) * C_ + c0 + txx] = __float2half_rn(tile[txx][tyy + i * 8]);
    }
}

// ---------------------------------------------------------------------------
// mgemm2<TERMS, HACC>: fp16 operands, K-stage 64, 2 buffers, cp.async.
// 64 MMAs + 24 ldsm per warp between barriers (2x the old K32 scheme).
// ---------------------------------------------------------------------------
template <int TERMS, int HACC>
__global__ __launch_bounds__(256, 2)
void mgemm2_kernel(const __half* __restrict__ WhiG, const __half* __restrict__ WloG,
                   const __half* __restrict__ Xg, __half* __restrict__ Outg,
                   float* __restrict__ OutF32, const float* __restrict__ bias,
                   int M, int K, int N, int hbits,
                   long long sWb, long long sWh,
                   long long sXb, long long sXh,
                   long long sOb, long long sOh)
{
    extern __shared__ __align__(16) char smraw[];
    const uint32_t smb = smem_u32(smraw);

    constexpr int NTILE = TERMS + 1;            // Whi [,Wlo], X
    constexpr int STG   = NTILE * MG_TILE;      // words per stage
    constexpr int XOFFW = (TERMS == 2) ? 2 * MG_TILE : MG_TILE;

    const int z = blockIdx.z;
    const int zb = z >> hbits;
    const int zh = z & ((1 << hbits) - 1);
    const __half* Whp = WhiG + (size_t)zb * sWb + (size_t)zh * sWh;
    const __half* Wlp = (TERMS == 2) ? WloG + (size_t)zb * sWb + (size_t)zh * sWh : nullptr;
    const __half* Xp  = Xg + (size_t)zb * sXb + (size_t)zh * sXh;
    const size_t obase = (size_t)zb * sOb + (size_t)zh * sOh;

    const int m0 = blockIdx.y * 128;
    const int n0 = blockIdx.x * 128;
    const int tid  = threadIdx.x;
    const int lane = tid & 31;
    const int wid  = tid >> 5;
    const int wm = wid >> 2;
    const int wn = wid & 3;
    const int g  = lane >> 2;
    const int cc = lane & 3;

    const int rr = lane & 7;
    const int mi = lane >> 3;
    const uint32_t aR8 = (mi & 1) * 8, aK4 = (mi >> 1) * 4;
    const uint32_t bR8 = (mi >> 1) * 8, bK4 = (mi & 1) * 4;

    const int sr    = tid & 127;   // row
    const int shalf = tid >> 7;    // 0/1 -> 64B half of 128B row

    float acc[4][4][4];
    uint32_t acc2[4][4][2];
#pragma unroll
    for (int mt = 0; mt < 4; ++mt)
#pragma unroll
        for (int nt = 0; nt < 4; ++nt) {
            if (HACC) { acc2[mt][nt][0] = 0u; acc2[mt][nt][1] = 0u; }
            else {
#pragma unroll
                for (int e = 0; e < 4; ++e) acc[mt][nt][e] = 0.f;
            }
        }

    auto stage = [&](int ks, int buf) {
        const int k0 = ks * 64;
        const __half* wh = Whp + (size_t)(m0 + sr) * K + k0 + shalf * 32;
        const __half* xs = Xp  + (size_t)(n0 + sr) * K + k0 + shalf * 32;
        uint32_t base = smb + (buf * STG + sr * SW64) * 4 + shalf * 64;
        cp16(base,      wh);      cp16(base + 16, wh + 8);
        cp16(base + 32, wh + 16); cp16(base + 48, wh + 24);
        uint32_t bx = base + XOFFW * 4;
        cp16(bx,      xs);      cp16(bx + 16, xs + 8);
        cp16(bx + 32, xs + 16); cp16(bx + 48, xs + 24);
        if (TERMS == 2) {
            const __half* wl = Wlp + (size_t)(m0 + sr) * K + k0 + shalf * 32;
            uint32_t bl = base + MG_TILE * 4;
            cp16(bl,      wl);      cp16(bl + 16, wl + 8);
            cp16(bl + 32, wl + 16); cp16(bl + 48, wl + 24);
        }
    };

    const int steps = K / 64;
    stage(0, 0); CP_COMMIT();
    if (steps > 1) { stage(1, 1); CP_COMMIT(); }

    for (int ks = 0; ks < steps; ++ks) {
        if (ks + 1 < steps) CP_WAIT1();
        else                CP_WAIT0();
        __syncthreads();

        const uint32_t bb  = smb + (ks & 1) * STG * 4;
        const uint32_t wHi = bb;
        const uint32_t wLo = bb + MG_TILE * 4;
        const uint32_t xB  = bb + XOFFW * 4;

#pragma unroll
        for (int h16 = 0; h16 < 4; ++h16) {
            const uint32_t ko = h16 * 8;
            uint32_t bh[2][4];
#pragma unroll
            for (int np = 0; np < 2; ++np) {
                uint32_t off = ((wn * 32 + np * 16 + bR8 + rr) * SW64 + ko + bK4) * 4;
                ldsm4(bh[np], xB + off);
            }
#pragma unroll
            for (int mt = 0; mt < 4; ++mt) {
                uint32_t offA = ((wm * 64 + mt * 16 + aR8 + rr) * SW64 + ko + aK4) * 4;
                uint32_t ah[4], al[4];
                ldsm4(ah, wHi + offA);
                if (TERMS == 2) ldsm4(al, wLo + offA);
#pragma unroll
                for (int nt = 0; nt < 4; ++nt) {
                    const int np = nt >> 1, sub = nt & 1;
                    if (HACC) {
                        mma16816hh(acc2[mt][nt], ah, &bh[np][sub * 2]);
                    } else {
                        mma16816h(acc[mt][nt], ah, &bh[np][sub * 2]);
                        if (TERMS == 2) mma16816h(acc[mt][nt], al, &bh[np][sub * 2]);
                    }
                }
            }
        }
        __syncthreads();
        if (ks + 2 < steps) { stage(ks + 2, ks & 1); CP_COMMIT(); }
    }

    if (OutF32 != nullptr) {
        float* Op = OutF32 + obase;
#pragma unroll
        for (int mt = 0; mt < 4; ++mt)
#pragma unroll
            for (int nt = 0; nt < 4; ++nt) {
                int r = m0 + wm * 64 + mt * 16 + g;
                int c = n0 + wn * 32 + nt * 8 + 2 * cc;
                float b0 = bias ? bias[r] : 0.f;
                float b1 = bias ? bias[r + 8] : 0.f;
                float2 v;
                v.x = acc[mt][nt][0] + b0; v.y = acc[mt][nt][1] + b0;
                *reinterpret_cast<float2*>(Op + (size_t)r * N + c) = v;
                v.x = acc[mt][nt][2] + b1; v.y = acc[mt][nt][3] + b1;
                *reinterpret_cast<float2*>(Op + (size_t)(r + 8) * N + c) = v;
            }
    } else {
        __half* Op = Outg + obase;
#pragma unroll
        for (int mt = 0; mt < 4; ++mt)
#pragma unroll
            for (int nt = 0; nt < 4; ++nt) {
                int r = m0 + wm * 64 + mt * 16 + g;
                int c = n0 + wn * 32 + nt * 8 + 2 * cc;
                if (HACC) {
                    *reinterpret_cast<uint32_t*>(Op + (size_t)r * N + c) = acc2[mt][nt][0];
                    *reinterpret_cast<uint32_t*>(Op + (size_t)(r + 8) * N + c) = acc2[mt][nt][1];
                } else {
                    *reinterpret_cast<__half2*>(Op + (size_t)r * N + c) =
                        __floats2half2_rn(acc[mt][nt][0], acc[mt][nt][1]);
                    *reinterpret_cast<__half2*>(Op + (size_t)(r + 8) * N + c) =
                        __floats2half2_rn(acc[mt][nt][2], acc[mt][nt][3]);
                }
            }
    }
}

// ---------------------------------------------------------------------------
// Fused attention (unchanged from round 15): phase A fp16-accum, packed-fp16
// softmax, stmatrix Pa store, cross-tile prefetch, V double-buffered.
// ---------------------------------------------------------------------------
__global__ __launch_bounds__(256, 2)
void attn_kernel()
{
    extern __shared__ __align__(16) char smraw[];
    uint32_t* SMw = reinterpret_cast<uint32_t*>(smraw);
    const uint32_t smb = smem_u32(smraw);

    const int chunk = blockIdx.x;
    const int h     = blockIdx.y;
    const int b     = blockIdx.z;

    const size_t pRowBase = (size_t)(b * HEADS + h) * DK;
    const size_t xRowBase = (size_t)b * N_ + chunk * CHUNKSZ;
    const size_t vRowBase = (size_t)b * VC + h * DV;
    __half* OpT = g_o2T + ((size_t)b * N_ + chunk * CHUNKSZ) * VC + h * DV;

    const int tid  = threadIdx.x;
    const int lane = tid & 31;
    const int wid  = tid >> 5;
    const int wm = wid >> 2;
    const int wn = wid & 3;
    const int g  = lane >> 2;
    const int cc = lane & 3;

    const int rr = lane & 7;
    const int mi = lane >> 3;
    const uint32_t aR8 = (mi & 1) * 8, aK4 = (mi >> 1) * 4;
    const uint32_t bR8 = (mi >> 1) * 8, bK4 = (mi & 1) * 4;

    const int sr    = tid & 127;
    const int shalf = tid >> 7;
    const int vd    = tid & 63;
    const int vq    = tid >> 6;

    const int stJ = lane & 7;
    const int stI = ((lane >> 3) & 1) * 8;

    const __half2 kk2 = __float2half2_rn(0.03125f * 1.4426950408889634f);

    float oacc[2][4][4];
#pragma unroll
    for (int mt = 0; mt < 2; ++mt)
#pragma unroll
        for (int nt = 0; nt < 4; ++nt)
#pragma unroll
            for (int e = 0; e < 4; ++e) oacc[mt][nt][e] = 0.f;

    float* rsum = reinterpret_cast<float*>(SMw + OFF_RED);
    const uint32_t aPa = smb;

    auto stagePX = [&](int i0, int c0, int bsel) {
        const __half* srcP = g_Pf + (pRowBase + i0 + sr) * C_ + c0 + shalf * 32;
        const __half* srcX = g_Xf + (xRowBase + sr) * C_ + c0 + shalf * 32;
        uint32_t dP = smb + (bsel * BUFW + sr * SW64) * 4 + shalf * 64;
        uint32_t dX = dP + 128 * SW64 * 4;
        cp16(dP,      srcP);      cp16(dP + 16, srcP + 8);
        cp16(dP + 32, srcP + 16); cp16(dP + 48, srcP + 24);
        cp16(dX,      srcX);      cp16(dX + 16, srcX + 8);
        cp16(dX + 32, srcX + 16); cp16(dX + 48, srcX + 24);
    };
    auto stageV = [&](int i0, int vb) {
        const __half* srcV = g_Vf + (vRowBase + vd) * N_ + i0 + vq * 32;
        uint32_t dV = smb + (OFF_V + vb * VBUFW + vd * SWV) * 4 + vq * 64;
#pragma unroll
        for (int q = 0; q < 4; ++q)
            cp16(dV + q * 16, srcV + q * 8);
    };

    stageV(0, 0);
    stagePX(0, 0, 1);
    CP_COMMIT();
    int vb = 0;

    for (int it = 0; it < 8; ++it) {
        const int i0 = it * 128;

        stagePX(i0, 64, 0);
        CP_COMMIT();

        // ========== Phase A: fp16-accumulator MMA ==========
        uint32_t sacc2[4][4][2];
#pragma unroll
        for (int mt = 0; mt < 4; ++mt)
#pragma unroll
            for (int nt = 0; nt < 4; ++nt) {
                sacc2[mt][nt][0] = 0u; sacc2[mt][nt][1] = 0u;
            }

#pragma unroll
        for (int s = 0; s < 4; ++s) {
            if (s < 3) CP_WAIT1();
            else       CP_WAIT0();
            __syncthreads();

            const int buf = (s & 1) ^ 1;
            const uint32_t pB = smb + buf * BUFW * 4;
            const uint32_t xB = pB + 128 * SW64 * 4;

#pragma unroll
            for (int h16 = 0; h16 < 4; ++h16) {
                const uint32_t ko = h16 * 8;
                uint32_t bh[2][4];
#pragma unroll
                for (int np = 0; np < 2; ++np) {
                    uint32_t off = ((wn * 32 + np * 16 + bR8 + rr) * SW64 + ko + bK4) * 4;
                    ldsm4(bh[np], xB + off);
                }
#pragma unroll
                for (int mt = 0; mt < 4; ++mt) {
                    uint32_t offA = ((wm * 64 + mt * 16 + aR8 + rr) * SW64 + ko + aK4) * 4;
                    uint32_t ah[4];
                    ldsm4(ah, pB + offA);
#pragma unroll
                    for (int nt = 0; nt < 4; ++nt)
                        mma16816hh(sacc2[mt][nt], ah, &bh[nt >> 1][(nt & 1) * 2]);
                }
            }
            __syncthreads();

            if (s == 0) { stagePX(i0, 128, 1); CP_COMMIT(); }
            if (s == 1) { stagePX(i0, 192, 0); CP_COMMIT(); }
        }

        // ===== softmax: packed fp16 exp2, row-sum in fp32 =====
#pragma unroll
        for (int mt = 0; mt < 4; ++mt) {
            int r0 = wm * 64 + mt * 16 + g;
            float s0 = 0.f, s1 = 0.f;
#pragma unroll
            for (int nt = 0; nt < 4; ++nt) {
                __half2 e01 = h2exp2(__hmul2(*reinterpret_cast<__half2*>(&sacc2[mt][nt][0]), kk2));
                __half2 e23 = h2exp2(__hmul2(*reinterpret_cast<__half2*>(&sacc2[mt][nt][1]), kk2));
                sacc2[mt][nt][0] = *reinterpret_cast<uint32_t*>(&e01);
                sacc2[mt][nt][1] = *reinterpret_cast<uint32_t*>(&e23);
                float2 f01 = __half22float2(e01);
                float2 f23 = __half22float2(e23);
                s0 += f01.x + f01.y;
                s1 += f23.x + f23.y;
            }
            s0 += __shfl_xor_sync(0xffffffffu, s0, 1);
            s0 += __shfl_xor_sync(0xffffffffu, s0, 2);
            s1 += __shfl_xor_sync(0xffffffffu, s1, 1);
            s1 += __shfl_xor_sync(0xffffffffu, s1, 2);
            if (cc == 0) {
                rsum[r0 * 4 + wn] = s0;
                rsum[(r0 + 8) * 4 + wn] = s1;
            }
        }
        __syncthreads();
        // normalize + transposed store via movmatrix/stmatrix (Pa aliases b0)
#pragma unroll
        for (int mt = 0; mt < 4; ++mt) {
            int r0 = wm * 64 + mt * 16 + g;
            int ib = wm * 64 + mt * 16;
            float4 q0 = *reinterpret_cast<float4*>(&rsum[r0 * 4]);
            float4 q1 = *reinterpret_cast<float4*>(&rsum[(r0 + 8) * 4]);
            __half2 hi0 = __float2half2_rn(1.0f / (q0.x + q0.y + q0.z + q0.w));
            __half2 hi1 = __float2half2_rn(1.0f / (q1.x + q1.y + q1.z + q1.w));
#pragma unroll
            for (int nt = 0; nt < 4; ++nt) {
                __half2 p01 = __hmul2(*reinterpret_cast<__half2*>(&sacc2[mt][nt][0]), hi0);
                __half2 p23 = __hmul2(*reinterpret_cast<__half2*>(&sacc2[mt][nt][1]), hi1);
                uint32_t t0 = movm_t(*reinterpret_cast<uint32_t*>(&p01));
                uint32_t t1 = movm_t(*reinterpret_cast<uint32_t*>(&p23));
                int jb = wn * 32 + nt * 8;
                uint32_t addr = aPa + (uint32_t)(jb + stJ) * (SWP * 4)
                              + (uint32_t)(ib + stI) * 2;
                stsm2(addr, t0, t1);
            }
        }
        __syncthreads();

        if (it < 7) {
            stageV(i0 + 128, vb ^ 1);
            stagePX(i0 + 128, 0, 1);
            CP_COMMIT();
        }

        // ========== Phase B: fp32-accum (output precision) ==========
        const uint32_t aV = smb + (OFF_V + vb * VBUFW) * 4;
#pragma unroll
        for (int ks = 0; ks < 8; ++ks) {
            const uint32_t ko = ks * 8;
            uint32_t bh[2][4];
#pragma unroll
            for (int np = 0; np < 2; ++np) {
                uint32_t off = ((wn * 32 + np * 16 + bR8 + rr) * SWP + ko + bK4) * 4;
                ldsm4(bh[np], aPa + off);
            }
#pragma unroll
            for (int mt = 0; mt < 2; ++mt) {
                uint32_t offA = ((wm * 32 + mt * 16 + aR8 + rr) * SWV + ko + aK4) * 4;
                uint32_t ah[4];
                ldsm4(ah, aV + offA);
#pragma unroll
                for (int nt = 0; nt < 4; ++nt)
                    mma16816h(oacc[mt][nt], ah, &bh[nt >> 1][(nt & 1) * 2]);
            }
        }
        __syncthreads();
        vb ^= 1;
    }

    CP_WAIT0();

#pragma unroll
    for (int mt = 0; mt < 2; ++mt)
#pragma unroll
        for (int nt = 0; nt < 4; ++nt) {
            int d = wm * 32 + mt * 16 + g;
            int j = wn * 32 + nt * 8 + 2 * cc;
            OpT[(size_t)j * VC + d]           = __float2half_rn(oacc[mt][nt][0]);
            OpT[(size_t)(j + 1) * VC + d]     = __float2half_rn(oacc[mt][nt][1]);
            OpT[(size_t)j * VC + d + 8]       = __float2half_rn(oacc[mt][nt][2]);
            OpT[(size_t)(j + 1) * VC + d + 8] = __float2half_rn(oacc[mt][nt][3]);
        }
}

// ---------------------------------------------------------------------------
// Launch
// ---------------------------------------------------------------------------
extern "C" void kernel_launch(void* const* d_in, const int* in_sizes, int n_in,
                              void* d_out, int out_size)
{
    const float* x  = (const float*)d_in[0];
    const float* Wk = (const float*)d_in[1];
    const float* Wq = (const float*)d_in[2];
    const float* Wv = (const float*)d_in[3];
    const float* Wr = (const float*)d_in[4];
    const float* br = (const float*)d_in[5];
    float* out = (float*)d_out;

    __half *gA2, *gPf, *gVf, *gXf16, *gx16, *go2T;
    __half *gWqThi, *gWkhi, *gWvhi, *gWvlo, *gWrhi, *gWrlo;
    cudaGetSymbolAddress((void**)&gA2,    g_A2f);
    cudaGetSymbolAddress((void**)&gPf,    g_Pf);
    cudaGetSymbolAddress((void**)&gVf,    g_Vf);
    cudaGetSymbolAddress((void**)&gXf16,  g_Xf);
    cudaGetSymbolAddress((void**)&gx16,   g_x16);
    cudaGetSymbolAddress((void**)&go2T,   g_o2T);
    cudaGetSymbolAddress((void**)&gWqThi, g_WqThi);
    cudaGetSymbolAddress((void**)&gWkhi,  g_Wkhi);
    cudaGetSymbolAddress((void**)&gWvhi,  g_Wvhi);
    cudaGetSymbolAddress((void**)&gWvlo,  g_Wvlo);
    cudaGetSymbolAddress((void**)&gWrhi,  g_Wrhi);
    cudaGetSymbolAddress((void**)&gWrlo,  g_Wrlo);

    dim3 blk(256);
    const int smem1 = 2 * (2 * MG_TILE) * 4;   // 1-term: 2 buffers x {Whi,X} = 73728
    const int smem2 = 2 * (3 * MG_TILE) * 4;   // 2-term: 2 buffers x {Whi,Wlo,X} = 110592
    cudaFuncSetAttribute((const void*)mgemm2_kernel<1, 1>,
                         cudaFuncAttributeMaxDynamicSharedMemorySize, smem1);
    cudaFuncSetAttribute((const void*)mgemm2_kernel<2, 0>,
                         cudaFuncAttributeMaxDynamicSharedMemorySize, smem2);

    // 1. elementwise prep
    prep_elem_kernel<<<(F4_TOTAL + 255) / 256, blk>>>(Wk, Wv, Wr, x);

    // 2. Wq^T fp16
    prep_wqt_kernel<<<dim3(DK / 32, C_ / 32, HEADS), blk>>>(Wq);

    // 3. x^T fp16 [b][j][c]
    xsplit_kernel<<<dim3(N_ / 32, C_ / 32, B_), blk>>>(x);

    // 4. A2[b,h] = Wq_h^T @ x_b^T : [c'][c] fp16 (1-term, fp16 accum)
    mgemm2_kernel<1, 1><<<dim3(C_ / 128, C_ / 128, B_ * HEADS), blk, smem1>>>(
        gWqThi, nullptr, gx16, gA2, nullptr, nullptr,
        C_, N_, C_, 3,
        0, (long long)C_ * DK,
        (long long)C_ * N_, 0,
        (long long)HEADS * C_ * C_, (long long)C_ * C_);

    // 5. P[b,h] = Wk_h @ A : [i][c'] fp16 (1-term, fp16 accum)
    mgemm2_kernel<1, 1><<<dim3(C_ / 128, DK / 128, B_ * HEADS), blk, smem1>>>(
        gWkhi, nullptr, gA2, gPf, nullptr, nullptr,
        DK, C_, C_, 3,
        0, (long long)DK * C_,
        (long long)HEADS * C_ * C_, (long long)C_ * C_,
        (long long)HEADS * DK * C_, (long long)DK * C_);

    // 6. v = Wv @ x_b : [d][j] fp16 (2-term, fp32 accum)
    mgemm2_kernel<2, 0><<<dim3(N_ / 128, VC / 128, B_), blk, smem2>>>(
        gWvhi, gWvlo, gXf16, gVf, nullptr, nullptr,
        VC, C_, N_, 0,
        0, 0,
        (long long)N_ * C_, 0,
        (long long)VC * N_, 0);

    // 7. fused attention -> O^T fp16
    const int attn_smem = SMEM_WORDS_ATTN * 4;
    cudaFuncSetAttribute(attn_kernel, cudaFuncAttributeMaxDynamicSharedMemorySize, attn_smem);
    attn_kernel<<<dim3(NCHUNK, HEADS, B_), blk, attn_smem>>>();

    // 8. y = Wr @ o2 + br : fp32 out (2-term, fp32 accum)
    mgemm2_kernel<2, 0><<<dim3(N_ / 128, C_ / 128, B_), blk, smem2>>>(
        gWrhi, gWrlo, go2T, nullptr, out, br,
        C_, VC, N_, 0,
        0, 0,
        (long long)N_ * VC, 0,
        (long long)C_ * N_, 0);
}

// round 17
// speedup vs baseline: 1.1028x; 1.1028x over previous
#include <cuda_runtime.h>
#include <cuda_bf16.h>
#include <cuda_fp16.h>
#include <cstdint>

// Problem constants (fixed shapes from setup_inputs)
static constexpr int B_    = 8;
static constexpr int C_    = 256;
static constexpr int N_    = 1024;   // T*H*W
static constexpr int HEADS = 8;
static constexpr int DK    = 1024;   // KC / heads
static constexpr int DV    = 64;     // VC / heads
static constexpr int KC    = 8192;
static constexpr int VC    = 512;
static constexpr int CHUNKSZ = 128;
static constexpr int NCHUNK  = 8;

// Device scratch (no cudaMalloc allowed)
__device__ __half g_A2f[(size_t)B_ * HEADS * C_ * C_];     // A^T fp16 [b,h][c'][c]
__device__ __half g_Pf[(size_t)B_ * HEADS * DK * C_];      // P fp16 [b,h][i][c']
__device__ __half g_Vf[(size_t)B_ * VC * N_];              // V fp16 [b][d][i]
__device__ __half g_Xf[(size_t)B_ * N_ * C_];              // x^T fp16 [b][j][c]
__device__ __half g_x16[(size_t)B_ * C_ * N_];             // x fp16 [b][c][j]
__device__ __half g_o2T[(size_t)B_ * N_ * VC];             // O^T fp16 [b][j][d]
__device__ __half g_WqThi[(size_t)HEADS * C_ * DK];        // Wq^T fp16 [h][c'][m]
__device__ __half g_Wkhi[(size_t)KC * C_];                 // Wk fp16 [dk][c]
__device__ __half g_Wvhi[(size_t)VC * C_];
__device__ __half g_Wvlo[(size_t)VC * C_];
__device__ __half g_Wrhi[(size_t)C_ * VC];
__device__ __half g_Wrlo[(size_t)C_ * VC];

// ---------------------------------------------------------------------------
// Helpers
// ---------------------------------------------------------------------------
__device__ __forceinline__ float fp16hi(float f)
{
    return __half2float(__float2half_rn(f));
}
__device__ __forceinline__ uint32_t packh(float lo_el, float hi_el)
{
    __half2 h = __floats2half2_rn(lo_el, hi_el);
    return *reinterpret_cast<uint32_t*>(&h);
}
__device__ __forceinline__ void mma16816h(float* d, const uint32_t* a, const uint32_t* b)
{
    asm volatile(
        "mma.sync.aligned.m16n8k16.row.col.f32.f16.f16.f32 "
        "{%0,%1,%2,%3}, {%4,%5,%6,%7}, {%8,%9}, {%0,%1,%2,%3};"
        : "+f"(d[0]), "+f"(d[1]), "+f"(d[2]), "+f"(d[3])
        : "r"(a[0]), "r"(a[1]), "r"(a[2]), "r"(a[3]), "r"(b[0]), "r"(b[1]));
}
// fp16-accumulator MMA
__device__ __forceinline__ void mma16816hh(uint32_t* d, const uint32_t* a, const uint32_t* b)
{
    asm volatile(
        "mma.sync.aligned.m16n8k16.row.col.f16.f16.f16.f16 "
        "{%0,%1}, {%2,%3,%4,%5}, {%6,%7}, {%0,%1};"
        : "+r"(d[0]), "+r"(d[1])
        : "r"(a[0]), "r"(a[1]), "r"(a[2]), "r"(a[3]), "r"(b[0]), "r"(b[1]));
}
__device__ __forceinline__ void ldsm4(uint32_t* r, uint32_t a)
{
    asm volatile("ldmatrix.sync.aligned.m8n8.x4.shared.b16 {%0,%1,%2,%3}, [%4];"
                 : "=r"(r[0]), "=r"(r[1]), "=r"(r[2]), "=r"(r[3]) : "r"(a));
}
__device__ __forceinline__ uint32_t movm_t(uint32_t a)
{
    uint32_t d;
    asm("movmatrix.sync.aligned.m8n8.trans.b16 %0, %1;" : "=r"(d) : "r"(a));
    return d;
}
__device__ __forceinline__ void stsm2(uint32_t addr, uint32_t r0, uint32_t r1)
{
    asm volatile("stmatrix.sync.aligned.m8n8.x2.shared.b16 [%0], {%1,%2};"
                 :: "r"(addr), "r"(r0), "r"(r1) : "memory");
}
__device__ __forceinline__ uint32_t smem_u32(const void* p)
{
    uint32_t a;
    asm("{ .reg .u64 t; cvta.to.shared.u64 t, %1; cvt.u32.u64 %0, t; }"
        : "=r"(a) : "l"(p));
    return a;
}
__device__ __forceinline__ void cp16(uint32_t dst, const void* src)
{
    asm volatile("cp.async.cg.shared.global [%0], [%1], 16;"
                 :: "r"(dst), "l"(src));
}
#define CP_COMMIT() asm volatile("cp.async.commit_group;" ::: "memory")
#define CP_WAIT1()  asm volatile("cp.async.wait_group 1;" ::: "memory")
#define CP_WAIT0()  asm volatile("cp.async.wait_group 0;" ::: "memory")

// smem strides (u32 words)
static constexpr int SW   = 20;  // 16 payload + 4 pad
static constexpr int SW64 = 36;  // 32 payload + 4 pad
static constexpr int SWP  = 68;  // 64 payload + 4 pad
static constexpr int SWV  = 68;

// attn smem layout (u32 word offsets)
static constexpr int BUFW    = 2 * 128 * SW64;            // 9216 per buffer (P+X)
static constexpr int OFF_V   = 2 * BUFW;                  // 18432; 2 V buffers
static constexpr int VBUFW   = 64 * SWV;                  // 4352 per V buffer
static constexpr int OFF_RED = OFF_V + 2 * VBUFW;         // 27136
static constexpr int SMEM_WORDS_ATTN = OFF_RED + 512;     // 27648 words = 110592 B
// Pa tile (128*SWP = 8704 words) aliases buffer0.

// ---------------------------------------------------------------------------
// Prep: elementwise fp16 conversions
// ---------------------------------------------------------------------------
static constexpr int F4_WK = (KC * C_) / 4;
static constexpr int F4_WV = (VC * C_) / 4;
static constexpr int F4_WR = (C_ * VC) / 4;
static constexpr int F4_X  = (B_ * C_ * N_) / 4;
static constexpr int F4_TOTAL = F4_WK + F4_WV + F4_WR + F4_X;

__global__ __launch_bounds__(256)
void prep_elem_kernel(const float* __restrict__ Wk, const float* __restrict__ Wv,
                      const float* __restrict__ Wr, const float* __restrict__ x)
{
    int i4 = blockIdx.x * 256 + threadIdx.x;
    if (i4 >= F4_TOTAL) return;
    if (i4 < F4_WK) {
        float4 f = reinterpret_cast<const float4*>(Wk)[i4];
        uint32_t* H = reinterpret_cast<uint32_t*>(g_Wkhi);
        H[i4 * 2]     = packh(f.x, f.y);
        H[i4 * 2 + 1] = packh(f.z, f.w);
        return;
    }
    const float* src;
    uint32_t *H, *L;
    int j4;
    if (i4 < F4_WK + F4_WV) {
        j4 = i4 - F4_WK; src = Wv;
        H = reinterpret_cast<uint32_t*>(g_Wvhi);
        L = reinterpret_cast<uint32_t*>(g_Wvlo);
    } else if (i4 < F4_WK + F4_WV + F4_WR) {
        j4 = i4 - F4_WK - F4_WV; src = Wr;
        H = reinterpret_cast<uint32_t*>(g_Wrhi);
        L = reinterpret_cast<uint32_t*>(g_Wrlo);
    } else {
        j4 = i4 - F4_WK - F4_WV - F4_WR;
        float4 f = reinterpret_cast<const float4*>(x)[j4];
        uint32_t* Hx = reinterpret_cast<uint32_t*>(g_x16);
        Hx[j4 * 2]     = packh(f.x, f.y);
        Hx[j4 * 2 + 1] = packh(f.z, f.w);
        return;
    }
    float4 f = reinterpret_cast<const float4*>(src)[j4];
    float h0 = fp16hi(f.x), h1 = fp16hi(f.y), h2 = fp16hi(f.z), h3 = fp16hi(f.w);
    H[j4 * 2]     = packh(h0, h1);
    H[j4 * 2 + 1] = packh(h2, h3);
    L[j4 * 2]     = packh(f.x - h0, f.y - h1);
    L[j4 * 2 + 1] = packh(f.z - h2, f.w - h3);
}

// ---------------------------------------------------------------------------
// Prep: Wq^T fp16
// ---------------------------------------------------------------------------
__global__ __launch_bounds__(256)
void prep_wqt_kernel(const float* __restrict__ Wq)
{
    __shared__ float tile[32][33];
    const int h  = blockIdx.z;
    const int c0 = blockIdx.y * 32;
    const int m0 = blockIdx.x * 32;
    const int txx = threadIdx.x & 31;
    const int tyy = threadIdx.x >> 5;

#pragma unroll
    for (int i = 0; i < 4; ++i) {
        int m = m0 + tyy + i * 8;
        tile[tyy + i * 8][txx] = Wq[(size_t)(h * DK + m) * C_ + c0 + txx];
    }
    __syncthreads();
#pragma unroll
    for (int i = 0; i < 4; ++i) {
        int c = c0 + tyy + i * 8;
        g_WqThi[((size_t)h * C_ + c) * DK + m0 + txx] =
            __float2half_rn(tile[txx][tyy + i * 8]);
    }
}

// ---------------------------------------------------------------------------
// x transpose: x [b][c][j] fp32 -> g_Xf [b][j][c] fp16
// ---------------------------------------------------------------------------
__global__ __launch_bounds__(256)
void xsplit_kernel(const float* __restrict__ x)
{
    __shared__ float tile[32][33];
    const int b  = blockIdx.z;
    const int c0 = blockIdx.y * 32;
    const int j0 = blockIdx.x * 32;
    const int txx = threadIdx.x & 31;
    const int tyy = threadIdx.x >> 5;

#pragma unroll
    for (int i = 0; i < 4; ++i) {
        int c = c0 + tyy + i * 8;
        tile[tyy + i * 8][txx] = x[((size_t)b * C_ + c) * N_ + j0 + txx];
    }
    __syncthreads();
#pragma unroll
    for (int i = 0; i < 4; ++i) {
        int j = j0 + tyy + i * 8;
        g_Xf[((size_t)b * N_ + j) * C_ + c0 + txx] = __float2half_rn(tile[txx][tyy + i * 8]);
    }
}

// ---------------------------------------------------------------------------
// mgemm2<TERMS, HACC>: fp16 operands, K-stage 32, 3-buffer cp.async pipeline
// (single sync per K-stage).  [round-15 proven version]
// ---------------------------------------------------------------------------
template <int TERMS, int HACC>
__global__ __launch_bounds__(256, 2)
void mgemm2_kernel(const __half* __restrict__ WhiG, const __half* __restrict__ WloG,
                   const __half* __restrict__ Xg, __half* __restrict__ Outg,
                   float* __restrict__ OutF32, const float* __restrict__ bias,
                   int M, int K, int N, int hbits,
                   long long sWb, long long sWh,
                   long long sXb, long long sXh,
                   long long sOb, long long sOh)
{
    extern __shared__ __align__(16) char smraw[];
    const uint32_t smb = smem_u32(smraw);

    constexpr int STG  = (TERMS == 2) ? 3 * 128 * SW : 2 * 128 * SW;
    constexpr int XOFF = (TERMS == 2) ? 5120 : 2560;

    const int z = blockIdx.z;
    const int zb = z >> hbits;
    const int zh = z & ((1 << hbits) - 1);
    const __half* Whp = WhiG + (size_t)zb * sWb + (size_t)zh * sWh;
    const __half* Wlp = (TERMS == 2) ? WloG + (size_t)zb * sWb + (size_t)zh * sWh : nullptr;
    const __half* Xp  = Xg + (size_t)zb * sXb + (size_t)zh * sXh;
    const size_t obase = (size_t)zb * sOb + (size_t)zh * sOh;

    const int m0 = blockIdx.y * 128;
    const int n0 = blockIdx.x * 128;
    const int tid  = threadIdx.x;
    const int lane = tid & 31;
    const int wid  = tid >> 5;
    const int wm = wid >> 2;
    const int wn = wid & 3;
    const int g  = lane >> 2;
    const int cc = lane & 3;

    const int rr = lane & 7;
    const int mi = lane >> 3;
    const uint32_t aR8 = (mi & 1) * 8, aK4 = (mi >> 1) * 4;
    const uint32_t bR8 = (mi >> 1) * 8, bK4 = (mi & 1) * 4;

    const int row  = tid >> 1;
    const int half = tid & 1;

    float acc[4][4][4];
    uint32_t acc2[4][4][2];
#pragma unroll
    for (int mt = 0; mt < 4; ++mt)
#pragma unroll
        for (int nt = 0; nt < 4; ++nt) {
            if (HACC) { acc2[mt][nt][0] = 0u; acc2[mt][nt][1] = 0u; }
            else {
#pragma unroll
                for (int e = 0; e < 4; ++e) acc[mt][nt][e] = 0.f;
            }
        }

    auto stage = [&](int ks, int buf) {
        const int k0 = ks * 32;
        const __half* wh = Whp + (size_t)(m0 + row) * K + k0 + half * 16;
        const __half* xs = Xp  + (size_t)(n0 + row) * K + k0 + half * 16;
        uint32_t base = smb + (buf * STG + row * SW) * 4 + half * 32;
        cp16(base, wh);            cp16(base + 16, wh + 8);
        cp16(base + XOFF * 4, xs); cp16(base + XOFF * 4 + 16, xs + 8);
        if (TERMS == 2) {
            const __half* wl = Wlp + (size_t)(m0 + row) * K + k0 + half * 16;
            cp16(base + 2560 * 4, wl); cp16(base + 2560 * 4 + 16, wl + 8);
        }
    };

    const int steps = K / 32;
    stage(0, 0); CP_COMMIT();
    stage(1, 1); CP_COMMIT();

    int rb = 0;
    for (int ks = 0; ks < steps; ++ks) {
        if (ks + 1 < steps) CP_WAIT1();
        else                CP_WAIT0();
        __syncthreads();

        const uint32_t bb  = smb + rb * STG * 4;
        const uint32_t wHi = bb;
        const uint32_t wLo = bb + 2560 * 4;
        const uint32_t xB  = bb + XOFF * 4;

#pragma unroll
        for (int h16 = 0; h16 < 2; ++h16) {
            const uint32_t ko = h16 * 8;
            uint32_t bh[2][4];
#pragma unroll
            for (int np = 0; np < 2; ++np) {
                uint32_t off = ((wn * 32 + np * 16 + bR8 + rr) * SW + ko + bK4) * 4;
                ldsm4(bh[np], xB + off);
            }
#pragma unroll
            for (int mt = 0; mt < 4; ++mt) {
                uint32_t offA = ((wm * 64 + mt * 16 + aR8 + rr) * SW + ko + aK4) * 4;
                uint32_t ah[4], al[4];
                ldsm4(ah, wHi + offA);
                if (TERMS == 2) ldsm4(al, wLo + offA);
#pragma unroll
                for (int nt = 0; nt < 4; ++nt) {
                    const int np = nt >> 1, sub = nt & 1;
                    if (HACC) {
                        mma16816hh(acc2[mt][nt], ah, &bh[np][sub * 2]);
                    } else {
                        mma16816h(acc[mt][nt], ah, &bh[np][sub * 2]);
                        if (TERMS == 2) mma16816h(acc[mt][nt], al, &bh[np][sub * 2]);
                    }
                }
            }
        }
        if (ks + 2 < steps) {
            int wbuf = rb + 2; if (wbuf >= 3) wbuf -= 3;
            stage(ks + 2, wbuf); CP_COMMIT();
        }
        if (++rb == 3) rb = 0;
    }

    if (OutF32 != nullptr) {
        float* Op = OutF32 + obase;
#pragma unroll
        for (int mt = 0; mt < 4; ++mt)
#pragma unroll
            for (int nt = 0; nt < 4; ++nt) {
                int r = m0 + wm * 64 + mt * 16 + g;
                int c = n0 + wn * 32 + nt * 8 + 2 * cc;
                float b0 = bias ? bias[r] : 0.f;
                float b1 = bias ? bias[r + 8] : 0.f;
                float2 v;
                v.x = acc[mt][nt][0] + b0; v.y = acc[mt][nt][1] + b0;
                *reinterpret_cast<float2*>(Op + (size_t)r * N + c) = v;
                v.x = acc[mt][nt][2] + b1; v.y = acc[mt][nt][3] + b1;
                *reinterpret_cast<float2*>(Op + (size_t)(r + 8) * N + c) = v;
            }
    } else {
        __half* Op = Outg + obase;
#pragma unroll
        for (int mt = 0; mt < 4; ++mt)
#pragma unroll
            for (int nt = 0; nt < 4; ++nt) {
                int r = m0 + wm * 64 + mt * 16 + g;
                int c = n0 + wn * 32 + nt * 8 + 2 * cc;
                if (HACC) {
                    *reinterpret_cast<uint32_t*>(Op + (size_t)r * N + c) = acc2[mt][nt][0];
                    *reinterpret_cast<uint32_t*>(Op + (size_t)(r + 8) * N + c) = acc2[mt][nt][1];
                } else {
                    *reinterpret_cast<__half2*>(Op + (size_t)r * N + c) =
                        __floats2half2_rn(acc[mt][nt][0], acc[mt][nt][1]);
                    *reinterpret_cast<__half2*>(Op + (size_t)(r + 8) * N + c) =
                        __floats2half2_rn(acc[mt][nt][2], acc[mt][nt][3]);
                }
            }
    }
}

// ---------------------------------------------------------------------------
// Fused attention: 2 chunks per CTA (grid 256 -> single co-resident wave).
// Per chunk: phase A fp16-accum, packed-fp16 softmax, stmatrix Pa store,
// cross-tile prefetch, V double-buffered, phase B fp32-accum.
// ---------------------------------------------------------------------------
__global__ __launch_bounds__(256, 2)
void attn_kernel()
{
    extern __shared__ __align__(16) char smraw[];
    uint32_t* SMw = reinterpret_cast<uint32_t*>(smraw);
    const uint32_t smb = smem_u32(smraw);

    const int h = blockIdx.y;
    const int b = blockIdx.z;

    const size_t pRowBase = (size_t)(b * HEADS + h) * DK;
    const size_t vRowBase = (size_t)b * VC + h * DV;

    const int tid  = threadIdx.x;
    const int lane = tid & 31;
    const int wid  = tid >> 5;
    const int wm = wid >> 2;
    const int wn = wid & 3;
    const int g  = lane >> 2;
    const int cc = lane & 3;

    const int rr = lane & 7;
    const int mi = lane >> 3;
    const uint32_t aR8 = (mi & 1) * 8, aK4 = (mi >> 1) * 4;
    const uint32_t bR8 = (mi >> 1) * 8, bK4 = (mi & 1) * 4;

    const int sr    = tid & 127;
    const int shalf = tid >> 7;
    const int vd    = tid & 63;
    const int vq    = tid >> 6;

    const int stJ = lane & 7;
    const int stI = ((lane >> 3) & 1) * 8;

    const __half2 kk2 = __float2half2_rn(0.03125f * 1.4426950408889634f);

    float* rsum = reinterpret_cast<float*>(SMw + OFF_RED);
    const uint32_t aPa = smb;

    for (int cj = 0; cj < 2; ++cj) {
        const int chunk = blockIdx.x * 2 + cj;
        const size_t xRowBase = (size_t)b * N_ + chunk * CHUNKSZ;
        __half* OpT = g_o2T + ((size_t)b * N_ + chunk * CHUNKSZ) * VC + h * DV;

        auto stagePX = [&](int i0, int c0, int bsel) {
            const __half* srcP = g_Pf + (pRowBase + i0 + sr) * C_ + c0 + shalf * 32;
            const __half* srcX = g_Xf + (xRowBase + sr) * C_ + c0 + shalf * 32;
            uint32_t dP = smb + (bsel * BUFW + sr * SW64) * 4 + shalf * 64;
            uint32_t dX = dP + 128 * SW64 * 4;
            cp16(dP,      srcP);      cp16(dP + 16, srcP + 8);
            cp16(dP + 32, srcP + 16); cp16(dP + 48, srcP + 24);
            cp16(dX,      srcX);      cp16(dX + 16, srcX + 8);
            cp16(dX + 32, srcX + 16); cp16(dX + 48, srcX + 24);
        };
        auto stageV = [&](int i0, int vb) {
            const __half* srcV = g_Vf + (vRowBase + vd) * N_ + i0 + vq * 32;
            uint32_t dV = smb + (OFF_V + vb * VBUFW + vd * SWV) * 4 + vq * 64;
#pragma unroll
            for (int q = 0; q < 4; ++q)
                cp16(dV + q * 16, srcV + q * 8);
        };

        float oacc[2][4][4];
#pragma unroll
        for (int mt = 0; mt < 2; ++mt)
#pragma unroll
            for (int nt = 0; nt < 4; ++nt)
#pragma unroll
                for (int e = 0; e < 4; ++e) oacc[mt][nt][e] = 0.f;

        stageV(0, 0);
        stagePX(0, 0, 1);
        CP_COMMIT();
        int vb = 0;

        for (int it = 0; it < 8; ++it) {
            const int i0 = it * 128;

            stagePX(i0, 64, 0);
            CP_COMMIT();

            // ========== Phase A: fp16-accumulator MMA ==========
            uint32_t sacc2[4][4][2];
#pragma unroll
            for (int mt = 0; mt < 4; ++mt)
#pragma unroll
                for (int nt = 0; nt < 4; ++nt) {
                    sacc2[mt][nt][0] = 0u; sacc2[mt][nt][1] = 0u;
                }

#pragma unroll
            for (int s = 0; s < 4; ++s) {
                if (s < 3) CP_WAIT1();
                else       CP_WAIT0();
                __syncthreads();

                const int buf = (s & 1) ^ 1;
                const uint32_t pB = smb + buf * BUFW * 4;
                const uint32_t xB = pB + 128 * SW64 * 4;

#pragma unroll
                for (int h16 = 0; h16 < 4; ++h16) {
                    const uint32_t ko = h16 * 8;
                    uint32_t bh[2][4];
#pragma unroll
                    for (int np = 0; np < 2; ++np) {
                        uint32_t off = ((wn * 32 + np * 16 + bR8 + rr) * SW64 + ko + bK4) * 4;
                        ldsm4(bh[np], xB + off);
                    }
#pragma unroll
                    for (int mt = 0; mt < 4; ++mt) {
                        uint32_t offA = ((wm * 64 + mt * 16 + aR8 + rr) * SW64 + ko + aK4) * 4;
                        uint32_t ah[4];
                        ldsm4(ah, pB + offA);
#pragma unroll
                        for (int nt = 0; nt < 4; ++nt)
                            mma16816hh(sacc2[mt][nt], ah, &bh[nt >> 1][(nt & 1) * 2]);
                    }
                }
                __syncthreads();

                if (s == 0) { stagePX(i0, 128, 1); CP_COMMIT(); }
                if (s == 1) { stagePX(i0, 192, 0); CP_COMMIT(); }
            }

            // ===== softmax: packed fp16 exp2, row-sum in fp32 =====
#pragma unroll
            for (int mt = 0; mt < 4; ++mt) {
                int r0 = wm * 64 + mt * 16 + g;
                float s0 = 0.f, s1 = 0.f;
#pragma unroll
                for (int nt = 0; nt < 4; ++nt) {
                    __half2 e01 = h2exp2(__hmul2(*reinterpret_cast<__half2*>(&sacc2[mt][nt][0]), kk2));
                    __half2 e23 = h2exp2(__hmul2(*reinterpret_cast<__half2*>(&sacc2[mt][nt][1]), kk2));
                    sacc2[mt][nt][0] = *reinterpret_cast<uint32_t*>(&e01);
                    sacc2[mt][nt][1] = *reinterpret_cast<uint32_t*>(&e23);
                    float2 f01 = __half22float2(e01);
                    float2 f23 = __half22float2(e23);
                    s0 += f01.x + f01.y;
                    s1 += f23.x + f23.y;
                }
                s0 += __shfl_xor_sync(0xffffffffu, s0, 1);
                s0 += __shfl_xor_sync(0xffffffffu, s0, 2);
                s1 += __shfl_xor_sync(0xffffffffu, s1, 1);
                s1 += __shfl_xor_sync(0xffffffffu, s1, 2);
                if (cc == 0) {
                    rsum[r0 * 4 + wn] = s0;
                    rsum[(r0 + 8) * 4 + wn] = s1;
                }
            }
            __syncthreads();
            // normalize + transposed store via movmatrix/stmatrix (Pa aliases b0)
#pragma unroll
            for (int mt = 0; mt < 4; ++mt) {
                int r0 = wm * 64 + mt * 16 + g;
                int ib = wm * 64 + mt * 16;
                float4 q0 = *reinterpret_cast<float4*>(&rsum[r0 * 4]);
                float4 q1 = *reinterpret_cast<float4*>(&rsum[(r0 + 8) * 4]);
                __half2 hi0 = __float2half2_rn(1.0f / (q0.x + q0.y + q0.z + q0.w));
                __half2 hi1 = __float2half2_rn(1.0f / (q1.x + q1.y + q1.z + q1.w));
#pragma unroll
                for (int nt = 0; nt < 4; ++nt) {
                    __half2 p01 = __hmul2(*reinterpret_cast<__half2*>(&sacc2[mt][nt][0]), hi0);
                    __half2 p23 = __hmul2(*reinterpret_cast<__half2*>(&sacc2[mt][nt][1]), hi1);
                    uint32_t t0 = movm_t(*reinterpret_cast<uint32_t*>(&p01));
                    uint32_t t1 = movm_t(*reinterpret_cast<uint32_t*>(&p23));
                    int jb = wn * 32 + nt * 8;
                    uint32_t addr = aPa + (uint32_t)(jb + stJ) * (SWP * 4)
                                  + (uint32_t)(ib + stI) * 2;
                    stsm2(addr, t0, t1);
                }
            }
            __syncthreads();

            if (it < 7) {
                stageV(i0 + 128, vb ^ 1);
                stagePX(i0 + 128, 0, 1);
                CP_COMMIT();
            }

            // ========== Phase B: fp32-accum (output precision) ==========
            const uint32_t aV = smb + (OFF_V + vb * VBUFW) * 4;
#pragma unroll
            for (int ks = 0; ks < 8; ++ks) {
                const uint32_t ko = ks * 8;
                uint32_t bh[2][4];
#pragma unroll
                for (int np = 0; np < 2; ++np) {
                    uint32_t off = ((wn * 32 + np * 16 + bR8 + rr) * SWP + ko + bK4) * 4;
                    ldsm4(bh[np], aPa + off);
                }
#pragma unroll
                for (int mt = 0; mt < 2; ++mt) {
                    uint32_t offA = ((wm * 32 + mt * 16 + aR8 + rr) * SWV + ko + aK4) * 4;
                    uint32_t ah[4];
                    ldsm4(ah, aV + offA);
#pragma unroll
                    for (int nt = 0; nt < 4; ++nt)
                        mma16816h(oacc[mt][nt], ah, &bh[nt >> 1][(nt & 1) * 2]);
                }
            }
            __syncthreads();
            vb ^= 1;
        }

        CP_WAIT0();
        __syncthreads();   // buffers quiet before next chunk re-stages

        // ---- write O transposed [j][d] fp16 ----
#pragma unroll
        for (int mt = 0; mt < 2; ++mt)
#pragma unroll
            for (int nt = 0; nt < 4; ++nt) {
                int d = wm * 32 + mt * 16 + g;
                int j = wn * 32 + nt * 8 + 2 * cc;
                OpT[(size_t)j * VC + d]           = __float2half_rn(oacc[mt][nt][0]);
                OpT[(size_t)(j + 1) * VC + d]     = __float2half_rn(oacc[mt][nt][1]);
                OpT[(size_t)j * VC + d + 8]       = __float2half_rn(oacc[mt][nt][2]);
                OpT[(size_t)(j + 1) * VC + d + 8] = __float2half_rn(oacc[mt][nt][3]);
            }
    }
}

// ---------------------------------------------------------------------------
// Launch
// ---------------------------------------------------------------------------
extern "C" void kernel_launch(void* const* d_in, const int* in_sizes, int n_in,
                              void* d_out, int out_size)
{
    const float* x  = (const float*)d_in[0];
    const float* Wk = (const float*)d_in[1];
    const float* Wq = (const float*)d_in[2];
    const float* Wv = (const float*)d_in[3];
    const float* Wr = (const float*)d_in[4];
    const float* br = (const float*)d_in[5];
    float* out = (float*)d_out;

    __half *gA2, *gPf, *gVf, *gXf16, *gx16, *go2T;
    __half *gWqThi, *gWkhi, *gWvhi, *gWvlo, *gWrhi, *gWrlo;
    cudaGetSymbolAddress((void**)&gA2,    g_A2f);
    cudaGetSymbolAddress((void**)&gPf,    g_Pf);
    cudaGetSymbolAddress((void**)&gVf,    g_Vf);
    cudaGetSymbolAddress((void**)&gXf16,  g_Xf);
    cudaGetSymbolAddress((void**)&gx16,   g_x16);
    cudaGetSymbolAddress((void**)&go2T,   g_o2T);
    cudaGetSymbolAddress((void**)&gWqThi, g_WqThi);
    cudaGetSymbolAddress((void**)&gWkhi,  g_Wkhi);
    cudaGetSymbolAddress((void**)&gWvhi,  g_Wvhi);
    cudaGetSymbolAddress((void**)&gWvlo,  g_Wvlo);
    cudaGetSymbolAddress((void**)&gWrhi,  g_Wrhi);
    cudaGetSymbolAddress((void**)&gWrlo,  g_Wrlo);

    dim3 blk(256);
    const int smem1 = 3 * (2 * 128 * SW) * 4;   // 1-term: 3 buffers
    const int smem2 = 3 * (3 * 128 * SW) * 4;   // 2-term: 3 buffers
    cudaFuncSetAttribute((const void*)mgemm2_kernel<1, 1>,
                         cudaFuncAttributeMaxDynamicSharedMemorySize, smem1);
    cudaFuncSetAttribute((const void*)mgemm2_kernel<2, 0>,
                         cudaFuncAttributeMaxDynamicSharedMemorySize, smem2);

    // 1. elementwise prep
    prep_elem_kernel<<<(F4_TOTAL + 255) / 256, blk>>>(Wk, Wv, Wr, x);

    // 2. Wq^T fp16
    prep_wqt_kernel<<<dim3(DK / 32, C_ / 32, HEADS), blk>>>(Wq);

    // 3. x^T fp16 [b][j][c]
    xsplit_kernel<<<dim3(N_ / 32, C_ / 32, B_), blk>>>(x);

    // 4. A2[b,h] = Wq_h^T @ x_b^T : [c'][c] fp16 (1-term, fp16 accum)
    mgemm2_kernel<1, 1><<<dim3(C_ / 128, C_ / 128, B_ * HEADS), blk, smem1>>>(
        gWqThi, nullptr, gx16, gA2, nullptr, nullptr,
        C_, N_, C_, 3,
        0, (long long)C_ * DK,
        (long long)C_ * N_, 0,
        (long long)HEADS * C_ * C_, (long long)C_ * C_);

    // 5. P[b,h] = Wk_h @ A : [i][c'] fp16 (1-term, fp16 accum)
    mgemm2_kernel<1, 1><<<dim3(C_ / 128, DK / 128, B_ * HEADS), blk, smem1>>>(
        gWkhi, nullptr, gA2, gPf, nullptr, nullptr,
        DK, C_, C_, 3,
        0, (long long)DK * C_,
        (long long)HEADS * C_ * C_, (long long)C_ * C_,
        (long long)HEADS * DK * C_, (long long)DK * C_);

    // 6. v = Wv @ x_b : [d][j] fp16 (2-term, fp32 accum)
    mgemm2_kernel<2, 0><<<dim3(N_ / 128, VC / 128, B_), blk, smem2>>>(
        gWvhi, gWvlo, gXf16, gVf, nullptr, nullptr,
        VC, C_, N_, 0,
        0, 0,
        (long long)N_ * C_, 0,
        (long long)VC * N_, 0);

    // 7. fused attention (2 chunks per CTA) -> O^T fp16
    const int attn_smem = SMEM_WORDS_ATTN * 4;
    cudaFuncSetAttribute(attn_kernel, cudaFuncAttributeMaxDynamicSharedMemorySize, attn_smem);
    attn_kernel<<<dim3(NCHUNK / 2, HEADS, B_), blk, attn_smem>>>();

    // 8. y = Wr @ o2 + br : fp32 out (2-term, fp32 accum)
    mgemm2_kernel<2, 0><<<dim3(N_ / 128, C_ / 128, B_), blk, smem2>>>(
        gWrhi, gWrlo, go2T, nullptr, out, br,
        C_, VC, N_, 0,
        0, 0,
        (long long)N_ * VC, 0,
        (long long)C_ * N_, 0);
}